// round 2
// baseline (speedup 1.0000x reference)
#include <cuda_runtime.h>
#include <cuda_bf16.h>
#include <cstdint>
#include <cstddef>

// Problem constants
#define BB 2
#define SS 2048
#define NH 8
#define DD 64
#define HID 512
#define NROWS (BB * SS)           // 4096
#define OUT_ELEMS (BB * SS * HID) // 2097152
#define NBH (BB * NH)             // 16

// ---------------- scratch (device globals; no allocation allowed) ----------------
__device__ float g_qh[NROWS * HID];
__device__ float g_kh[NROWS * HID];
__device__ float g_vh[NROWS * HID];
__device__ float g_ctx[NROWS * HID];
__device__ float2 g_stats[NBH * SS]; // (rowmax, rowsumexp)

// =====================================================================
// Kernel 1/5: projection SGEMM  Y[4096,512] = X[4096,512] @ W[512,512] + b
// BM=BN=128, BK=16, 256 threads, 8x8 per thread (split 4+4 layout)
// =====================================================================
__global__ __launch_bounds__(256) void proj_kernel(const float* __restrict__ X,
                                                   const float* __restrict__ W,
                                                   const float* __restrict__ bias,
                                                   float* __restrict__ Y) {
    __shared__ float sX[16][132]; // [k][row]  (transposed X tile)
    __shared__ float sW[16][132]; // [k][col]

    const int t = threadIdx.x;
    const int tx = t & 15, ty = t >> 4;
    const int row0 = blockIdx.y * 128;
    const int col0 = blockIdx.x * 128;

    // loader indices
    const int lr = t >> 1;          // X tile row 0..127
    const int lc = (t & 1) * 8;     // k offset 0/8
    const int wk = t >> 4;          // W k-row 0..15
    const int wc = (t & 15) * 8;    // W col offset

    float acc[8][8] = {};

    for (int kt = 0; kt < HID; kt += 16) {
        float4 x0 = *(const float4*)&X[(size_t)(row0 + lr) * HID + kt + lc];
        float4 x1 = *(const float4*)&X[(size_t)(row0 + lr) * HID + kt + lc + 4];
        float4 w0 = *(const float4*)&W[(size_t)(kt + wk) * HID + col0 + wc];
        float4 w1 = *(const float4*)&W[(size_t)(kt + wk) * HID + col0 + wc + 4];
        __syncthreads();
        sX[lc + 0][lr] = x0.x; sX[lc + 1][lr] = x0.y; sX[lc + 2][lr] = x0.z; sX[lc + 3][lr] = x0.w;
        sX[lc + 4][lr] = x1.x; sX[lc + 5][lr] = x1.y; sX[lc + 6][lr] = x1.z; sX[lc + 7][lr] = x1.w;
        *(float4*)&sW[wk][wc] = w0;
        *(float4*)&sW[wk][wc + 4] = w1;
        __syncthreads();
#pragma unroll
        for (int kk = 0; kk < 16; kk++) {
            float4 a0 = *(float4*)&sX[kk][ty * 4];
            float4 a1 = *(float4*)&sX[kk][64 + ty * 4];
            float4 b0 = *(float4*)&sW[kk][tx * 4];
            float4 b1 = *(float4*)&sW[kk][64 + tx * 4];
            float a[8] = {a0.x, a0.y, a0.z, a0.w, a1.x, a1.y, a1.z, a1.w};
            float b[8] = {b0.x, b0.y, b0.z, b0.w, b1.x, b1.y, b1.z, b1.w};
#pragma unroll
            for (int i = 0; i < 8; i++)
#pragma unroll
                for (int j = 0; j < 8; j++)
                    acc[i][j] = fmaf(a[i], b[j], acc[i][j]);
        }
    }

    float4 bv0 = *(const float4*)&bias[col0 + tx * 4];
    float4 bv1 = *(const float4*)&bias[col0 + 64 + tx * 4];
#pragma unroll
    for (int i = 0; i < 8; i++) {
        int rr = (i < 4) ? (ty * 4 + i) : (64 + ty * 4 + (i - 4));
        size_t base = (size_t)(row0 + rr) * HID;
        float4 o0, o1;
        o0.x = acc[i][0] + bv0.x; o0.y = acc[i][1] + bv0.y;
        o0.z = acc[i][2] + bv0.z; o0.w = acc[i][3] + bv0.w;
        o1.x = acc[i][4] + bv1.x; o1.y = acc[i][5] + bv1.y;
        o1.z = acc[i][6] + bv1.z; o1.w = acc[i][7] + bv1.w;
        *(float4*)&Y[base + col0 + tx * 4] = o0;
        *(float4*)&Y[base + col0 + 64 + tx * 4] = o1;
    }
}

// =====================================================================
// Kernel 2/5: raw masked logits  L[bh,q,k] = 0.125*(qh . kh) + bias ; mask -> -1e9
// Per CTA: 128 q-rows x 128 k-cols, K=64. Written into the scores output region.
// Mask is int32 (bool widened by the harness).
// =====================================================================
__global__ __launch_bounds__(256) void logits_kernel(const float* __restrict__ qh,
                                                     const float* __restrict__ kh,
                                                     const float* __restrict__ bias,
                                                     const int* __restrict__ mask,
                                                     float* __restrict__ L) {
    extern __shared__ float sm[];
    float* sQ = sm;            // [64][132] transposed [d][row]
    float* sK = sm + 64 * 132; // [64][132] transposed [d][col]

    const int t = threadIdx.x;
    const int tx = t & 15, ty = t >> 4;
    const int kt = blockIdx.x * 128;
    const int qt = blockIdx.y * 128;
    const int bh = blockIdx.z;
    const int b = bh >> 3, h = bh & 7;

    const float* Qb = qh + (size_t)b * SS * HID + h * DD;
    const float* Kb = kh + (size_t)b * SS * HID + h * DD;

#pragma unroll
    for (int i = 0; i < 8; i++) {
        int f4i = t + 256 * i;       // 0..2047
        int r = f4i >> 4;            // 0..127
        int d4 = (f4i & 15) * 4;     // 0..60
        float4 xq = *(const float4*)&Qb[(size_t)(qt + r) * HID + d4];
        sQ[(d4 + 0) * 132 + r] = xq.x; sQ[(d4 + 1) * 132 + r] = xq.y;
        sQ[(d4 + 2) * 132 + r] = xq.z; sQ[(d4 + 3) * 132 + r] = xq.w;
        float4 xk = *(const float4*)&Kb[(size_t)(kt + r) * HID + d4];
        sK[(d4 + 0) * 132 + r] = xk.x; sK[(d4 + 1) * 132 + r] = xk.y;
        sK[(d4 + 2) * 132 + r] = xk.z; sK[(d4 + 3) * 132 + r] = xk.w;
    }
    __syncthreads();

    float acc[8][8] = {};
#pragma unroll
    for (int d = 0; d < 64; d++) {
        float4 a0 = *(float4*)&sQ[d * 132 + ty * 4];
        float4 a1 = *(float4*)&sQ[d * 132 + 64 + ty * 4];
        float4 b0 = *(float4*)&sK[d * 132 + tx * 4];
        float4 b1 = *(float4*)&sK[d * 132 + 64 + tx * 4];
        float a[8] = {a0.x, a0.y, a0.z, a0.w, a1.x, a1.y, a1.z, a1.w};
        float bb2[8] = {b0.x, b0.y, b0.z, b0.w, b1.x, b1.y, b1.z, b1.w};
#pragma unroll
        for (int i = 0; i < 8; i++)
#pragma unroll
            for (int j = 0; j < 8; j++)
                acc[i][j] = fmaf(a[i], bb2[j], acc[i][j]);
    }

    const float scale = 0.125f; // D^-0.5
#pragma unroll
    for (int i = 0; i < 8; i++) {
        int rr = (i < 4) ? (ty * 4 + i) : (64 + ty * 4 + (i - 4));
        int qr = qt + rr;
        size_t boff = ((size_t)bh * SS + qr) * SS + kt;
        size_t moff = ((size_t)b * SS + qr) * SS + kt;
#pragma unroll
        for (int g = 0; g < 2; g++) {
            int c = g * 64 + tx * 4;
            float4 bv = *(const float4*)&bias[boff + c];
            int4 mv = *(const int4*)&mask[moff + c];
            float4 o;
            o.x = mv.x ? -1e9f : fmaf(acc[i][4 * g + 0], scale, bv.x);
            o.y = mv.y ? -1e9f : fmaf(acc[i][4 * g + 1], scale, bv.y);
            o.z = mv.z ? -1e9f : fmaf(acc[i][4 * g + 2], scale, bv.z);
            o.w = mv.w ? -1e9f : fmaf(acc[i][4 * g + 3], scale, bv.w);
            *(float4*)&L[boff + c] = o;
        }
    }
}

// =====================================================================
// Kernel 3/5: per-row softmax stats (max, sum exp). One warp per row.
// =====================================================================
__global__ __launch_bounds__(256) void stats_kernel(const float* __restrict__ L,
                                                    float2* __restrict__ st) {
    const int warp = threadIdx.x >> 5, lane = threadIdx.x & 31;
    const int row = blockIdx.x * 8 + warp; // 0..32767
    const float* p = L + (size_t)row * SS;

    float4 v[16];
    float m = -3.4e38f;
#pragma unroll
    for (int i = 0; i < 16; i++) {
        v[i] = *(const float4*)&p[i * 128 + lane * 4];
        m = fmaxf(m, fmaxf(fmaxf(v[i].x, v[i].y), fmaxf(v[i].z, v[i].w)));
    }
#pragma unroll
    for (int off = 16; off >= 1; off >>= 1)
        m = fmaxf(m, __shfl_xor_sync(0xFFFFFFFFu, m, off));

    float s = 0.f;
#pragma unroll
    for (int i = 0; i < 16; i++) {
        s += __expf(v[i].x - m) + __expf(v[i].y - m) +
             __expf(v[i].z - m) + __expf(v[i].w - m);
    }
#pragma unroll
    for (int off = 16; off >= 1; off >>= 1)
        s += __shfl_xor_sync(0xFFFFFFFFu, s, off);

    if (lane == 0) st[row] = make_float2(m, s);
}

// =====================================================================
// Kernel 4/5: normalize P in-place (final attention_scores output) + ctx = P @ V
// BM=128 rows, BN=64 (=D), BK=32, 128 threads, 8x8 per thread.
// =====================================================================
__global__ __launch_bounds__(128) void pv_kernel(float* __restrict__ P,
                                                 const float* __restrict__ vh,
                                                 const float2* __restrict__ st,
                                                 float* __restrict__ ctx) {
    __shared__ float sP[32 * 132]; // [key][row]
    __shared__ float sV[32 * 68];  // [key][col]
    __shared__ float sM[128], sIL[128];

    const int t = threadIdx.x;
    const int tx = t & 7, ty = t >> 3;
    const int qt = blockIdx.x * 128;
    const int bh = blockIdx.y;
    const int b = bh >> 3, h = bh & 7;

    {
        float2 s = st[bh * SS + qt + t];
        sM[t] = s.x;
        sIL[t] = 1.0f / s.y;
    }

    float acc[8][8] = {};
    float* Pb = P + ((size_t)bh * SS + qt) * SS;
    const float* Vb = vh + (size_t)b * SS * HID + h * DD;

    for (int k0 = 0; k0 < SS; k0 += 32) {
        __syncthreads();
        // load/normalize P tile 128x32, write back final P, stage transposed
#pragma unroll
        for (int i = 0; i < 8; i++) {
            int f4i = t + 128 * i;   // 0..1023
            int r = f4i >> 3;        // 0..127
            int c4 = (f4i & 7) * 4;  // 0..28
            size_t off = (size_t)r * SS + k0 + c4;
            float4 x = *(float4*)&Pb[off];
            float m = sM[r], il = sIL[r];
            float4 pv;
            pv.x = __expf(x.x - m) * il;
            pv.y = __expf(x.y - m) * il;
            pv.z = __expf(x.z - m) * il;
            pv.w = __expf(x.w - m) * il;
            *(float4*)&Pb[off] = pv;
            sP[(c4 + 0) * 132 + r] = pv.x;
            sP[(c4 + 1) * 132 + r] = pv.y;
            sP[(c4 + 2) * 132 + r] = pv.z;
            sP[(c4 + 3) * 132 + r] = pv.w;
        }
        // load V tile 32x64
#pragma unroll
        for (int i = 0; i < 4; i++) {
            int f4i = t + 128 * i;   // 0..511
            int kr = f4i >> 4;       // 0..31
            int c4 = (f4i & 15) * 4; // 0..60
            float4 x = *(const float4*)&Vb[(size_t)(k0 + kr) * HID + c4];
            *(float4*)&sV[kr * 68 + c4] = x;
        }
        __syncthreads();
#pragma unroll
        for (int kk = 0; kk < 32; kk++) {
            float4 a0 = *(float4*)&sP[kk * 132 + ty * 4];
            float4 a1 = *(float4*)&sP[kk * 132 + 64 + ty * 4];
            float4 b0 = *(float4*)&sV[kk * 68 + tx * 4];
            float4 b1 = *(float4*)&sV[kk * 68 + 32 + tx * 4];
            float a[8] = {a0.x, a0.y, a0.z, a0.w, a1.x, a1.y, a1.z, a1.w};
            float bb2[8] = {b0.x, b0.y, b0.z, b0.w, b1.x, b1.y, b1.z, b1.w};
#pragma unroll
            for (int i = 0; i < 8; i++)
#pragma unroll
                for (int j = 0; j < 8; j++)
                    acc[i][j] = fmaf(a[i], bb2[j], acc[i][j]);
        }
    }

#pragma unroll
    for (int i = 0; i < 8; i++) {
        int rr = (i < 4) ? (ty * 4 + i) : (64 + ty * 4 + (i - 4));
        size_t base = (size_t)(b * SS + qt + rr) * HID + h * DD;
        float4 o0 = {acc[i][0], acc[i][1], acc[i][2], acc[i][3]};
        float4 o1 = {acc[i][4], acc[i][5], acc[i][6], acc[i][7]};
        *(float4*)&ctx[base + tx * 4] = o0;
        *(float4*)&ctx[base + 32 + tx * 4] = o1;
    }
}

// =====================================================================
// Host launcher
// =====================================================================
extern "C" void kernel_launch(void* const* d_in, const int* in_sizes, int n_in,
                              void* d_out, int out_size) {
    const float* q = (const float*)d_in[0];
    const float* k = (const float*)d_in[1];
    const float* v = (const float*)d_in[2];
    const float* attn_bias = (const float*)d_in[3];
    const int* attn_mask = (const int*)d_in[4];
    const float* Wq = (const float*)d_in[5];
    const float* bq = (const float*)d_in[6];
    const float* Wk = (const float*)d_in[7];
    const float* bk = (const float*)d_in[8];
    const float* Wv = (const float*)d_in[9];
    const float* bv = (const float*)d_in[10];
    const float* Wo = (const float*)d_in[11];
    const float* bo = (const float*)d_in[12];

    float* out = (float*)d_out;
    float* scores = out + (size_t)OUT_ELEMS; // attention_scores region

    float *qh, *kh, *vh, *ctx;
    float2* stats;
    cudaGetSymbolAddress((void**)&qh, g_qh);
    cudaGetSymbolAddress((void**)&kh, g_kh);
    cudaGetSymbolAddress((void**)&vh, g_vh);
    cudaGetSymbolAddress((void**)&ctx, g_ctx);
    cudaGetSymbolAddress((void**)&stats, g_stats);

    dim3 pg(HID / 128, NROWS / 128); // (4, 32)
    proj_kernel<<<pg, 256>>>(q, Wq, bq, qh);
    proj_kernel<<<pg, 256>>>(k, Wk, bk, kh);
    proj_kernel<<<pg, 256>>>(v, Wv, bv, vh);

    const int lsmem = 2 * 64 * 132 * (int)sizeof(float); // 67584
    cudaFuncSetAttribute(logits_kernel, cudaFuncAttributeMaxDynamicSharedMemorySize, lsmem);
    dim3 lg(SS / 128, SS / 128, NBH); // (16,16,16)
    logits_kernel<<<lg, 256, lsmem>>>(qh, kh, attn_bias, attn_mask, scores);

    stats_kernel<<<(NBH * SS) / 8, 256>>>(scores, stats);

    dim3 vg(SS / 128, NBH); // (16,16)
    pv_kernel<<<vg, 128>>>(scores, vh, stats, ctx);

    proj_kernel<<<pg, 256>>>(ctx, Wo, bo, out);
}

// round 3
// speedup vs baseline: 1.0009x; 1.0009x over previous
#include <cuda_runtime.h>
#include <cuda_bf16.h>
#include <cstdint>
#include <cstddef>

// Problem constants
#define BB 2
#define SS 2048
#define NH 8
#define DD 64
#define HID 512
#define NROWS (BB * SS)           // 4096
#define OUT_ELEMS (BB * SS * HID) // 2097152
#define NBH (BB * NH)             // 16

// ---------------- scratch (device globals; no allocation allowed) ----------------
__device__ float g_qh[NROWS * HID];
__device__ float g_kh[NROWS * HID];
__device__ float g_vh[NROWS * HID];
__device__ float g_ctx[NROWS * HID];
__device__ float2 g_stats[NBH * SS]; // (rowmax, rowsumexp)

// Fast exp on the FMA pipe (no MUFU). exp(x) = 2^(x*log2e), 2^f via degree-7
// Taylor of 2^f on [0,1). Max rel err ~1.3e-6. Inputs here are always <= 0
// (x - rowmax); clamp at 2^-126 so masked (-1e9) values underflow to ~0.
__device__ __forceinline__ float fexp(float x) {
    float t = x * 1.4426950408889634f;
    t = fmaxf(t, -126.0f);
    float nf = floorf(t);
    float f = t - nf;
    float p = 1.5252733e-5f;
    p = fmaf(p, f, 1.5403530e-4f);
    p = fmaf(p, f, 1.3333558e-3f);
    p = fmaf(p, f, 9.6181291e-3f);
    p = fmaf(p, f, 5.5504109e-2f);
    p = fmaf(p, f, 2.4022651e-1f);
    p = fmaf(p, f, 6.9314718e-1f);
    p = fmaf(p, f, 1.0f);
    float s = __int_as_float(((int)nf + 127) << 23);
    return s * p;
}

// =====================================================================
// Kernel 1/5: projection SGEMM  Y[4096,512] = X[4096,512] @ W[512,512] + b
// =====================================================================
__global__ __launch_bounds__(256) void proj_kernel(const float* __restrict__ X,
                                                   const float* __restrict__ W,
                                                   const float* __restrict__ bias,
                                                   float* __restrict__ Y) {
    __shared__ float sX[16][132]; // [k][row]  (transposed X tile)
    __shared__ float sW[16][132]; // [k][col]

    const int t = threadIdx.x;
    const int tx = t & 15, ty = t >> 4;
    const int row0 = blockIdx.y * 128;
    const int col0 = blockIdx.x * 128;

    const int lr = t >> 1;          // X tile row 0..127
    const int lc = (t & 1) * 8;     // k offset 0/8
    const int wk = t >> 4;          // W k-row 0..15
    const int wc = (t & 15) * 8;    // W col offset

    float acc[8][8] = {};

    for (int kt = 0; kt < HID; kt += 16) {
        float4 x0 = *(const float4*)&X[(size_t)(row0 + lr) * HID + kt + lc];
        float4 x1 = *(const float4*)&X[(size_t)(row0 + lr) * HID + kt + lc + 4];
        float4 w0 = *(const float4*)&W[(size_t)(kt + wk) * HID + col0 + wc];
        float4 w1 = *(const float4*)&W[(size_t)(kt + wk) * HID + col0 + wc + 4];
        __syncthreads();
        sX[lc + 0][lr] = x0.x; sX[lc + 1][lr] = x0.y; sX[lc + 2][lr] = x0.z; sX[lc + 3][lr] = x0.w;
        sX[lc + 4][lr] = x1.x; sX[lc + 5][lr] = x1.y; sX[lc + 6][lr] = x1.z; sX[lc + 7][lr] = x1.w;
        *(float4*)&sW[wk][wc] = w0;
        *(float4*)&sW[wk][wc + 4] = w1;
        __syncthreads();
#pragma unroll
        for (int kk = 0; kk < 16; kk++) {
            float4 a0 = *(float4*)&sX[kk][ty * 4];
            float4 a1 = *(float4*)&sX[kk][64 + ty * 4];
            float4 b0 = *(float4*)&sW[kk][tx * 4];
            float4 b1 = *(float4*)&sW[kk][64 + tx * 4];
            float a[8] = {a0.x, a0.y, a0.z, a0.w, a1.x, a1.y, a1.z, a1.w};
            float b[8] = {b0.x, b0.y, b0.z, b0.w, b1.x, b1.y, b1.z, b1.w};
#pragma unroll
            for (int i = 0; i < 8; i++)
#pragma unroll
                for (int j = 0; j < 8; j++)
                    acc[i][j] = fmaf(a[i], b[j], acc[i][j]);
        }
    }

    float4 bv0 = *(const float4*)&bias[col0 + tx * 4];
    float4 bv1 = *(const float4*)&bias[col0 + 64 + tx * 4];
#pragma unroll
    for (int i = 0; i < 8; i++) {
        int rr = (i < 4) ? (ty * 4 + i) : (64 + ty * 4 + (i - 4));
        size_t base = (size_t)(row0 + rr) * HID;
        float4 o0, o1;
        o0.x = acc[i][0] + bv0.x; o0.y = acc[i][1] + bv0.y;
        o0.z = acc[i][2] + bv0.z; o0.w = acc[i][3] + bv0.w;
        o1.x = acc[i][4] + bv1.x; o1.y = acc[i][5] + bv1.y;
        o1.z = acc[i][6] + bv1.z; o1.w = acc[i][7] + bv1.w;
        *(float4*)&Y[base + col0 + tx * 4] = o0;
        *(float4*)&Y[base + col0 + 64 + tx * 4] = o1;
    }
}

// =====================================================================
// Kernel 2/5: raw masked logits (mask is int32)
// =====================================================================
__global__ __launch_bounds__(256) void logits_kernel(const float* __restrict__ qh,
                                                     const float* __restrict__ kh,
                                                     const float* __restrict__ bias,
                                                     const int* __restrict__ mask,
                                                     float* __restrict__ L) {
    extern __shared__ float sm[];
    float* sQ = sm;            // [64][132] transposed [d][row]
    float* sK = sm + 64 * 132; // [64][132] transposed [d][col]

    const int t = threadIdx.x;
    const int tx = t & 15, ty = t >> 4;
    const int kt = blockIdx.x * 128;
    const int qt = blockIdx.y * 128;
    const int bh = blockIdx.z;
    const int b = bh >> 3, h = bh & 7;

    const float* Qb = qh + (size_t)b * SS * HID + h * DD;
    const float* Kb = kh + (size_t)b * SS * HID + h * DD;

#pragma unroll
    for (int i = 0; i < 8; i++) {
        int f4i = t + 256 * i;       // 0..2047
        int r = f4i >> 4;            // 0..127
        int d4 = (f4i & 15) * 4;     // 0..60
        float4 xq = *(const float4*)&Qb[(size_t)(qt + r) * HID + d4];
        sQ[(d4 + 0) * 132 + r] = xq.x; sQ[(d4 + 1) * 132 + r] = xq.y;
        sQ[(d4 + 2) * 132 + r] = xq.z; sQ[(d4 + 3) * 132 + r] = xq.w;
        float4 xk = *(const float4*)&Kb[(size_t)(kt + r) * HID + d4];
        sK[(d4 + 0) * 132 + r] = xk.x; sK[(d4 + 1) * 132 + r] = xk.y;
        sK[(d4 + 2) * 132 + r] = xk.z; sK[(d4 + 3) * 132 + r] = xk.w;
    }
    __syncthreads();

    float acc[8][8] = {};
#pragma unroll
    for (int d = 0; d < 64; d++) {
        float4 a0 = *(float4*)&sQ[d * 132 + ty * 4];
        float4 a1 = *(float4*)&sQ[d * 132 + 64 + ty * 4];
        float4 b0 = *(float4*)&sK[d * 132 + tx * 4];
        float4 b1 = *(float4*)&sK[d * 132 + 64 + tx * 4];
        float a[8] = {a0.x, a0.y, a0.z, a0.w, a1.x, a1.y, a1.z, a1.w};
        float bb2[8] = {b0.x, b0.y, b0.z, b0.w, b1.x, b1.y, b1.z, b1.w};
#pragma unroll
        for (int i = 0; i < 8; i++)
#pragma unroll
            for (int j = 0; j < 8; j++)
                acc[i][j] = fmaf(a[i], bb2[j], acc[i][j]);
    }

    const float scale = 0.125f; // D^-0.5
#pragma unroll
    for (int i = 0; i < 8; i++) {
        int rr = (i < 4) ? (ty * 4 + i) : (64 + ty * 4 + (i - 4));
        int qr = qt + rr;
        size_t boff = ((size_t)bh * SS + qr) * SS + kt;
        size_t moff = ((size_t)b * SS + qr) * SS + kt;
#pragma unroll
        for (int g = 0; g < 2; g++) {
            int c = g * 64 + tx * 4;
            float4 bv = *(const float4*)&bias[boff + c];
            int4 mv = *(const int4*)&mask[moff + c];
            float4 o;
            o.x = mv.x ? -1e9f : fmaf(acc[i][4 * g + 0], scale, bv.x);
            o.y = mv.y ? -1e9f : fmaf(acc[i][4 * g + 1], scale, bv.y);
            o.z = mv.z ? -1e9f : fmaf(acc[i][4 * g + 2], scale, bv.z);
            o.w = mv.w ? -1e9f : fmaf(acc[i][4 * g + 3], scale, bv.w);
            *(float4*)&L[boff + c] = o;
        }
    }
}

// =====================================================================
// Kernel 3/5: per-row softmax stats (max, sum exp). One warp per row.
// =====================================================================
__global__ __launch_bounds__(256) void stats_kernel(const float* __restrict__ L,
                                                    float2* __restrict__ st) {
    const int warp = threadIdx.x >> 5, lane = threadIdx.x & 31;
    const int row = blockIdx.x * 8 + warp;
    const float* p = L + (size_t)row * SS;

    float4 v[16];
    float m = -3.4e38f;
#pragma unroll
    for (int i = 0; i < 16; i++) {
        v[i] = *(const float4*)&p[i * 128 + lane * 4];
        m = fmaxf(m, fmaxf(fmaxf(v[i].x, v[i].y), fmaxf(v[i].z, v[i].w)));
    }
#pragma unroll
    for (int off = 16; off >= 1; off >>= 1)
        m = fmaxf(m, __shfl_xor_sync(0xFFFFFFFFu, m, off));

    float s = 0.f;
#pragma unroll
    for (int i = 0; i < 16; i++) {
        s += fexp(v[i].x - m) + fexp(v[i].y - m) +
             fexp(v[i].z - m) + fexp(v[i].w - m);
    }
#pragma unroll
    for (int off = 16; off >= 1; off >>= 1)
        s += __shfl_xor_sync(0xFFFFFFFFu, s, off);

    if (lane == 0) st[row] = make_float2(m, s);
}

// =====================================================================
// Kernel 4/5: normalize P in-place + ctx = P @ V
// =====================================================================
__global__ __launch_bounds__(128) void pv_kernel(float* __restrict__ P,
                                                 const float* __restrict__ vh,
                                                 const float2* __restrict__ st,
                                                 float* __restrict__ ctx) {
    __shared__ float sP[32 * 132]; // [key][row]
    __shared__ float sV[32 * 68];  // [key][col]
    __shared__ float sM[128], sIL[128];

    const int t = threadIdx.x;
    const int tx = t & 7, ty = t >> 3;
    const int qt = blockIdx.x * 128;
    const int bh = blockIdx.y;
    const int b = bh >> 3, h = bh & 7;

    {
        float2 s = st[bh * SS + qt + t];
        sM[t] = s.x;
        sIL[t] = 1.0f / s.y;
    }

    float acc[8][8] = {};
    float* Pb = P + ((size_t)bh * SS + qt) * SS;
    const float* Vb = vh + (size_t)b * SS * HID + h * DD;

    for (int k0 = 0; k0 < SS; k0 += 32) {
        __syncthreads();
#pragma unroll
        for (int i = 0; i < 8; i++) {
            int f4i = t + 128 * i;   // 0..1023
            int r = f4i >> 3;        // 0..127
            int c4 = (f4i & 7) * 4;  // 0..28
            size_t off = (size_t)r * SS + k0 + c4;
            float4 x = *(float4*)&Pb[off];
            float m = sM[r], il = sIL[r];
            float4 pv;
            pv.x = fexp(x.x - m) * il;
            pv.y = fexp(x.y - m) * il;
            pv.z = fexp(x.z - m) * il;
            pv.w = fexp(x.w - m) * il;
            *(float4*)&Pb[off] = pv;
            sP[(c4 + 0) * 132 + r] = pv.x;
            sP[(c4 + 1) * 132 + r] = pv.y;
            sP[(c4 + 2) * 132 + r] = pv.z;
            sP[(c4 + 3) * 132 + r] = pv.w;
        }
#pragma unroll
        for (int i = 0; i < 4; i++) {
            int f4i = t + 128 * i;   // 0..511
            int kr = f4i >> 4;       // 0..31
            int c4 = (f4i & 15) * 4; // 0..60
            float4 x = *(const float4*)&Vb[(size_t)(k0 + kr) * HID + c4];
            *(float4*)&sV[kr * 68 + c4] = x;
        }
        __syncthreads();
#pragma unroll
        for (int kk = 0; kk < 32; kk++) {
            float4 a0 = *(float4*)&sP[kk * 132 + ty * 4];
            float4 a1 = *(float4*)&sP[kk * 132 + 64 + ty * 4];
            float4 b0 = *(float4*)&sV[kk * 68 + tx * 4];
            float4 b1 = *(float4*)&sV[kk * 68 + 32 + tx * 4];
            float a[8] = {a0.x, a0.y, a0.z, a0.w, a1.x, a1.y, a1.z, a1.w};
            float bb2[8] = {b0.x, b0.y, b0.z, b0.w, b1.x, b1.y, b1.z, b1.w};
#pragma unroll
            for (int i = 0; i < 8; i++)
#pragma unroll
                for (int j = 0; j < 8; j++)
                    acc[i][j] = fmaf(a[i], bb2[j], acc[i][j]);
        }
    }

#pragma unroll
    for (int i = 0; i < 8; i++) {
        int rr = (i < 4) ? (ty * 4 + i) : (64 + ty * 4 + (i - 4));
        size_t base = (size_t)(b * SS + qt + rr) * HID + h * DD;
        float4 o0 = {acc[i][0], acc[i][1], acc[i][2], acc[i][3]};
        float4 o1 = {acc[i][4], acc[i][5], acc[i][6], acc[i][7]};
        *(float4*)&ctx[base + tx * 4] = o0;
        *(float4*)&ctx[base + 32 + tx * 4] = o1;
    }
}

// =====================================================================
// Host launcher
// =====================================================================
extern "C" void kernel_launch(void* const* d_in, const int* in_sizes, int n_in,
                              void* d_out, int out_size) {
    const float* q = (const float*)d_in[0];
    const float* k = (const float*)d_in[1];
    const float* v = (const float*)d_in[2];
    const float* attn_bias = (const float*)d_in[3];
    const int* attn_mask = (const int*)d_in[4];
    const float* Wq = (const float*)d_in[5];
    const float* bq = (const float*)d_in[6];
    const float* Wk = (const float*)d_in[7];
    const float* bk = (const float*)d_in[8];
    const float* Wv = (const float*)d_in[9];
    const float* bv = (const float*)d_in[10];
    const float* Wo = (const float*)d_in[11];
    const float* bo = (const float*)d_in[12];

    float* out = (float*)d_out;
    float* scores = out + (size_t)OUT_ELEMS;

    float *qh, *kh, *vh, *ctx;
    float2* stats;
    cudaGetSymbolAddress((void**)&qh, g_qh);
    cudaGetSymbolAddress((void**)&kh, g_kh);
    cudaGetSymbolAddress((void**)&vh, g_vh);
    cudaGetSymbolAddress((void**)&ctx, g_ctx);
    cudaGetSymbolAddress((void**)&stats, g_stats);

    dim3 pg(HID / 128, NROWS / 128); // (4, 32)
    proj_kernel<<<pg, 256>>>(q, Wq, bq, qh);
    proj_kernel<<<pg, 256>>>(k, Wk, bk, kh);
    proj_kernel<<<pg, 256>>>(v, Wv, bv, vh);

    const int lsmem = 2 * 64 * 132 * (int)sizeof(float); // 67584
    cudaFuncSetAttribute(logits_kernel, cudaFuncAttributeMaxDynamicSharedMemorySize, lsmem);
    dim3 lg(SS / 128, SS / 128, NBH); // (16,16,16)
    logits_kernel<<<lg, 256, lsmem>>>(qh, kh, attn_bias, attn_mask, scores);

    stats_kernel<<<(NBH * SS) / 8, 256>>>(scores, stats);

    dim3 vg(SS / 128, NBH); // (16,16)
    pv_kernel<<<vg, 128>>>(scores, vh, stats, ctx);

    proj_kernel<<<pg, 256>>>(ctx, Wo, bo, out);
}

// round 4
// speedup vs baseline: 1.2555x; 1.2543x over previous
#include <cuda_runtime.h>
#include <cuda_bf16.h>
#include <cstdint>
#include <cstddef>

// Problem constants
#define BB 2
#define SS 2048
#define NH 8
#define DD 64
#define HID 512
#define NROWS (BB * SS)           // 4096
#define OUT_ELEMS (BB * SS * HID) // 2097152
#define NBH (BB * NH)             // 16
#define NKT (SS / 128)            // 16 k-tiles per row

// ---------------- scratch (device globals; no allocation allowed) ----------------
__device__ float g_qh[NROWS * HID];
__device__ float g_kh[NROWS * HID];
__device__ float g_vh[NROWS * HID];
__device__ float g_ctx0[NROWS * HID];
__device__ float g_ctx1[NROWS * HID];
__device__ float2 g_part[NBH * SS * NKT];  // per (row, ktile): (tile max, tile sumexp)
__device__ float g_scale[NBH * SS * NKT];  // per (row, ktile): exp(m_t - m) / l

// Fast exp on the FMA pipe. exp(x) = 2^(x*log2e). Max rel err ~1.3e-6.
// Clamped at 2^-126 so -1e9 inputs underflow to ~0.
__device__ __forceinline__ float fexp(float x) {
    float t = x * 1.4426950408889634f;
    t = fmaxf(t, -126.0f);
    float nf = floorf(t);
    float f = t - nf;
    float p = 1.5252733e-5f;
    p = fmaf(p, f, 1.5403530e-4f);
    p = fmaf(p, f, 1.3333558e-3f);
    p = fmaf(p, f, 9.6181291e-3f);
    p = fmaf(p, f, 5.5504109e-2f);
    p = fmaf(p, f, 2.4022651e-1f);
    p = fmaf(p, f, 6.9314718e-1f);
    p = fmaf(p, f, 1.0f);
    float s = __int_as_float(((int)nf + 127) << 23);
    return s * p;
}

// =====================================================================
// Kernel 1: projection SGEMM  Y = (X [+ X2]) @ W + b    (4096x512x512)
// =====================================================================
__global__ __launch_bounds__(256) void proj_kernel(const float* __restrict__ X,
                                                   const float* __restrict__ X2,
                                                   const float* __restrict__ W,
                                                   const float* __restrict__ bias,
                                                   float* __restrict__ Y) {
    __shared__ float sX[16][132];
    __shared__ float sW[16][132];

    const int t = threadIdx.x;
    const int tx = t & 15, ty = t >> 4;
    const int row0 = blockIdx.y * 128;
    const int col0 = blockIdx.x * 128;

    const int lr = t >> 1;
    const int lc = (t & 1) * 8;
    const int wk = t >> 4;
    const int wc = (t & 15) * 8;

    float acc[8][8] = {};

    for (int kt = 0; kt < HID; kt += 16) {
        size_t xo = (size_t)(row0 + lr) * HID + kt + lc;
        float4 x0 = *(const float4*)&X[xo];
        float4 x1 = *(const float4*)&X[xo + 4];
        if (X2) {
            float4 y0 = *(const float4*)&X2[xo];
            float4 y1 = *(const float4*)&X2[xo + 4];
            x0.x += y0.x; x0.y += y0.y; x0.z += y0.z; x0.w += y0.w;
            x1.x += y1.x; x1.y += y1.y; x1.z += y1.z; x1.w += y1.w;
        }
        float4 w0 = *(const float4*)&W[(size_t)(kt + wk) * HID + col0 + wc];
        float4 w1 = *(const float4*)&W[(size_t)(kt + wk) * HID + col0 + wc + 4];
        __syncthreads();
        sX[lc + 0][lr] = x0.x; sX[lc + 1][lr] = x0.y; sX[lc + 2][lr] = x0.z; sX[lc + 3][lr] = x0.w;
        sX[lc + 4][lr] = x1.x; sX[lc + 5][lr] = x1.y; sX[lc + 6][lr] = x1.z; sX[lc + 7][lr] = x1.w;
        *(float4*)&sW[wk][wc] = w0;
        *(float4*)&sW[wk][wc + 4] = w1;
        __syncthreads();
#pragma unroll
        for (int kk = 0; kk < 16; kk++) {
            float4 a0 = *(float4*)&sX[kk][ty * 4];
            float4 a1 = *(float4*)&sX[kk][64 + ty * 4];
            float4 b0 = *(float4*)&sW[kk][tx * 4];
            float4 b1 = *(float4*)&sW[kk][64 + tx * 4];
            float a[8] = {a0.x, a0.y, a0.z, a0.w, a1.x, a1.y, a1.z, a1.w};
            float b[8] = {b0.x, b0.y, b0.z, b0.w, b1.x, b1.y, b1.z, b1.w};
#pragma unroll
            for (int i = 0; i < 8; i++)
#pragma unroll
                for (int j = 0; j < 8; j++)
                    acc[i][j] = fmaf(a[i], b[j], acc[i][j]);
        }
    }

    float4 bv0 = *(const float4*)&bias[col0 + tx * 4];
    float4 bv1 = *(const float4*)&bias[col0 + 64 + tx * 4];
#pragma unroll
    for (int i = 0; i < 8; i++) {
        int rr = (i < 4) ? (ty * 4 + i) : (64 + ty * 4 + (i - 4));
        size_t base = (size_t)(row0 + rr) * HID;
        float4 o0, o1;
        o0.x = acc[i][0] + bv0.x; o0.y = acc[i][1] + bv0.y;
        o0.z = acc[i][2] + bv0.z; o0.w = acc[i][3] + bv0.w;
        o1.x = acc[i][4] + bv1.x; o1.y = acc[i][5] + bv1.y;
        o1.z = acc[i][6] + bv1.z; o1.w = acc[i][7] + bv1.w;
        *(float4*)&Y[base + col0 + tx * 4] = o0;
        *(float4*)&Y[base + col0 + 64 + tx * 4] = o1;
    }
}

// =====================================================================
// Kernel 2: fused logits + tile softmax stats.
// Writes E = exp(logit - m_tile) into scores region, and per-(row,ktile)
// partials (m_t, s_t).
// =====================================================================
__global__ __launch_bounds__(256) void logits_kernel(const float* __restrict__ qh,
                                                     const float* __restrict__ kh,
                                                     const float* __restrict__ bias,
                                                     const int* __restrict__ mask,
                                                     float* __restrict__ L,
                                                     float2* __restrict__ part) {
    extern __shared__ float sm[];
    float* sQ = sm;            // [64][132] transposed [d][row]
    float* sK = sm + 64 * 132; // [64][132] transposed [d][col]

    const int t = threadIdx.x;
    const int tx = t & 15, ty = t >> 4;
    const int kt = blockIdx.x * 128;
    const int ktile = blockIdx.x;
    const int qt = blockIdx.y * 128;
    const int bh = blockIdx.z;
    const int b = bh >> 3, h = bh & 7;

    const float* Qb = qh + (size_t)b * SS * HID + h * DD;
    const float* Kb = kh + (size_t)b * SS * HID + h * DD;

#pragma unroll
    for (int i = 0; i < 8; i++) {
        int f4i = t + 256 * i;
        int r = f4i >> 4;
        int d4 = (f4i & 15) * 4;
        float4 xq = *(const float4*)&Qb[(size_t)(qt + r) * HID + d4];
        sQ[(d4 + 0) * 132 + r] = xq.x; sQ[(d4 + 1) * 132 + r] = xq.y;
        sQ[(d4 + 2) * 132 + r] = xq.z; sQ[(d4 + 3) * 132 + r] = xq.w;
        float4 xk = *(const float4*)&Kb[(size_t)(kt + r) * HID + d4];
        sK[(d4 + 0) * 132 + r] = xk.x; sK[(d4 + 1) * 132 + r] = xk.y;
        sK[(d4 + 2) * 132 + r] = xk.z; sK[(d4 + 3) * 132 + r] = xk.w;
    }
    __syncthreads();

    float acc[8][8] = {};
#pragma unroll
    for (int d = 0; d < 64; d++) {
        float4 a0 = *(float4*)&sQ[d * 132 + ty * 4];
        float4 a1 = *(float4*)&sQ[d * 132 + 64 + ty * 4];
        float4 b0 = *(float4*)&sK[d * 132 + tx * 4];
        float4 b1 = *(float4*)&sK[d * 132 + 64 + tx * 4];
        float a[8] = {a0.x, a0.y, a0.z, a0.w, a1.x, a1.y, a1.z, a1.w};
        float bb2[8] = {b0.x, b0.y, b0.z, b0.w, b1.x, b1.y, b1.z, b1.w};
#pragma unroll
        for (int i = 0; i < 8; i++)
#pragma unroll
            for (int j = 0; j < 8; j++)
                acc[i][j] = fmaf(a[i], bb2[j], acc[i][j]);
    }

    const float scale = 0.125f;
#pragma unroll
    for (int i = 0; i < 8; i++) {
        int rr = (i < 4) ? (ty * 4 + i) : (64 + ty * 4 + (i - 4));
        int qr = qt + rr;
        size_t boff = ((size_t)bh * SS + qr) * SS + kt;
        size_t moff = ((size_t)b * SS + qr) * SS + kt;
        float val[8];
#pragma unroll
        for (int g = 0; g < 2; g++) {
            int c = g * 64 + tx * 4;
            float4 bv = *(const float4*)&bias[boff + c];
            int4 mv = *(const int4*)&mask[moff + c];
            val[4 * g + 0] = mv.x ? -1e9f : fmaf(acc[i][4 * g + 0], scale, bv.x);
            val[4 * g + 1] = mv.y ? -1e9f : fmaf(acc[i][4 * g + 1], scale, bv.y);
            val[4 * g + 2] = mv.z ? -1e9f : fmaf(acc[i][4 * g + 2], scale, bv.z);
            val[4 * g + 3] = mv.w ? -1e9f : fmaf(acc[i][4 * g + 3], scale, bv.w);
        }
        // tile row max across 16 lanes (tx group)
        float m = val[0];
#pragma unroll
        for (int j = 1; j < 8; j++) m = fmaxf(m, val[j]);
#pragma unroll
        for (int off = 8; off >= 1; off >>= 1)
            m = fmaxf(m, __shfl_xor_sync(0xFFFFFFFFu, m, off));
        // exp and tile row sum
        float e[8]; float s = 0.f;
#pragma unroll
        for (int j = 0; j < 8; j++) { e[j] = fexp(val[j] - m); s += e[j]; }
#pragma unroll
        for (int off = 8; off >= 1; off >>= 1)
            s += __shfl_xor_sync(0xFFFFFFFFu, s, off);

        float4 o0 = {e[0], e[1], e[2], e[3]};
        float4 o1 = {e[4], e[5], e[6], e[7]};
        *(float4*)&L[boff + tx * 4] = o0;
        *(float4*)&L[boff + 64 + tx * 4] = o1;
        if (tx == 0)
            part[((size_t)bh * SS + qr) * NKT + ktile] = make_float2(m, s);
    }
}

// =====================================================================
// Kernel 3: per-row reduce of tile partials -> per-(row,ktile) scale factor
// =====================================================================
__global__ __launch_bounds__(256) void reduce_kernel(const float2* __restrict__ part,
                                                     float* __restrict__ scl) {
    int row = blockIdx.x * 256 + threadIdx.x; // < NBH*SS
    float2 p[NKT];
    float m = -3.4e38f;
#pragma unroll
    for (int j = 0; j < NKT; j++) {
        p[j] = part[(size_t)row * NKT + j];
        m = fmaxf(m, p[j].x);
    }
    float e[NKT]; float l = 0.f;
#pragma unroll
    for (int j = 0; j < NKT; j++) {
        e[j] = fexp(p[j].x - m);
        l = fmaf(p[j].y, e[j], l);
    }
    float inv = 1.0f / l;
#pragma unroll
    for (int j = 0; j < NKT; j++)
        scl[(size_t)row * NKT + j] = e[j] * inv;
}

// =====================================================================
// Kernel 4: P = E * scale (written in-place, final attention_scores) and
// ctx_partial = P @ V over this CTA's K range. Split-K=2, 256 threads.
// Thread tile: 8 rows x 4 cols of the 128x64 CTA tile.
// =====================================================================
__global__ __launch_bounds__(256) void pv_kernel(float* __restrict__ P,
                                                 const float* __restrict__ vh,
                                                 const float* __restrict__ scl,
                                                 float* __restrict__ ctx0,
                                                 float* __restrict__ ctx1) {
    __shared__ float sE[32 * 132]; // [k][row]
    __shared__ float sV[32 * 68];  // [k][col]

    const int t = threadIdx.x;
    const int tx = t & 15, ty = t >> 4;
    const int qt = blockIdx.x * 128;
    const int bh = blockIdx.y;
    const int ks = blockIdx.z;
    const int b = bh >> 3, h = bh & 7;

    float* dst = ks ? ctx1 : ctx0;

    float acc[8][4] = {};
    float* Pb = P + ((size_t)bh * SS + qt) * SS;
    const float* Vb = vh + (size_t)b * SS * HID + h * DD;
    const float* Sb = scl + ((size_t)bh * SS + qt) * NKT;

    const int kbeg = ks * (SS / 2);
    for (int k0 = kbeg; k0 < kbeg + SS / 2; k0 += 32) {
        const int ktile = k0 >> 7;
        __syncthreads();
        // load E tile 128x32, scale to final P, write back, stage transposed
#pragma unroll
        for (int i = 0; i < 4; i++) {
            int idx = t + 256 * i;   // 0..1023
            int r = idx >> 3;        // 0..127
            int c4 = (idx & 7) * 4;  // 0..28
            size_t off = (size_t)r * SS + k0 + c4;
            float f = Sb[r * NKT + ktile];
            float4 x = *(float4*)&Pb[off];
            float4 pvv;
            pvv.x = x.x * f; pvv.y = x.y * f; pvv.z = x.z * f; pvv.w = x.w * f;
            *(float4*)&Pb[off] = pvv;
            sE[(c4 + 0) * 132 + r] = pvv.x;
            sE[(c4 + 1) * 132 + r] = pvv.y;
            sE[(c4 + 2) * 132 + r] = pvv.z;
            sE[(c4 + 3) * 132 + r] = pvv.w;
        }
        // load V tile 32x64
#pragma unroll
        for (int i = 0; i < 2; i++) {
            int idx = t + 256 * i;   // 0..511
            int kr = idx >> 4;       // 0..31
            int c4 = (idx & 15) * 4; // 0..60
            *(float4*)&sV[kr * 68 + c4] =
                *(const float4*)&Vb[(size_t)(k0 + kr) * HID + c4];
        }
        __syncthreads();
#pragma unroll
        for (int kk = 0; kk < 32; kk++) {
            float4 a0 = *(float4*)&sE[kk * 132 + ty * 4];
            float4 a1 = *(float4*)&sE[kk * 132 + 64 + ty * 4];
            float4 bv = *(float4*)&sV[kk * 68 + tx * 4];
            float a[8] = {a0.x, a0.y, a0.z, a0.w, a1.x, a1.y, a1.z, a1.w};
            float bb2[4] = {bv.x, bv.y, bv.z, bv.w};
#pragma unroll
            for (int i = 0; i < 8; i++)
#pragma unroll
                for (int j = 0; j < 4; j++)
                    acc[i][j] = fmaf(a[i], bb2[j], acc[i][j]);
        }
    }

#pragma unroll
    for (int i = 0; i < 8; i++) {
        int rr = (i < 4) ? (ty * 4 + i) : (64 + ty * 4 + (i - 4));
        size_t base = (size_t)(b * SS + qt + rr) * HID + h * DD + tx * 4;
        float4 o = {acc[i][0], acc[i][1], acc[i][2], acc[i][3]};
        *(float4*)&dst[base] = o;
    }
}

// =====================================================================
// Host launcher
// =====================================================================
extern "C" void kernel_launch(void* const* d_in, const int* in_sizes, int n_in,
                              void* d_out, int out_size) {
    const float* q = (const float*)d_in[0];
    const float* k = (const float*)d_in[1];
    const float* v = (const float*)d_in[2];
    const float* attn_bias = (const float*)d_in[3];
    const int* attn_mask = (const int*)d_in[4];
    const float* Wq = (const float*)d_in[5];
    const float* bq = (const float*)d_in[6];
    const float* Wk = (const float*)d_in[7];
    const float* bk = (const float*)d_in[8];
    const float* Wv = (const float*)d_in[9];
    const float* bv = (const float*)d_in[10];
    const float* Wo = (const float*)d_in[11];
    const float* bo = (const float*)d_in[12];

    float* out = (float*)d_out;
    float* scores = out + (size_t)OUT_ELEMS;

    float *qh, *kh, *vh, *ctx0, *ctx1, *scl;
    float2* part;
    cudaGetSymbolAddress((void**)&qh, g_qh);
    cudaGetSymbolAddress((void**)&kh, g_kh);
    cudaGetSymbolAddress((void**)&vh, g_vh);
    cudaGetSymbolAddress((void**)&ctx0, g_ctx0);
    cudaGetSymbolAddress((void**)&ctx1, g_ctx1);
    cudaGetSymbolAddress((void**)&part, g_part);
    cudaGetSymbolAddress((void**)&scl, g_scale);

    dim3 pg(HID / 128, NROWS / 128); // (4, 32)
    proj_kernel<<<pg, 256>>>(q, nullptr, Wq, bq, qh);
    proj_kernel<<<pg, 256>>>(k, nullptr, Wk, bk, kh);
    proj_kernel<<<pg, 256>>>(v, nullptr, Wv, bv, vh);

    const int lsmem = 2 * 64 * 132 * (int)sizeof(float); // 67584
    cudaFuncSetAttribute(logits_kernel, cudaFuncAttributeMaxDynamicSharedMemorySize, lsmem);
    dim3 lg(SS / 128, SS / 128, NBH); // (16,16,16)
    logits_kernel<<<lg, 256, lsmem>>>(qh, kh, attn_bias, attn_mask, scores, part);

    reduce_kernel<<<(NBH * SS) / 256, 256>>>(part, scl);

    dim3 vg(SS / 128, NBH, 2); // (16,16,2)
    pv_kernel<<<vg, 256>>>(scores, vh, scl, ctx0, ctx1);

    proj_kernel<<<pg, 256>>>(ctx0, ctx1, Wo, bo, out);
}